// round 11
// baseline (speedup 1.0000x reference)
#include <cuda_runtime.h>
#include <cuda_bf16.h>
#include <float.h>
#include <cstdint>

#define N_PTS 131072
#define K_EMB 1024
#define D_DIM 64
#define MT    128          // points per CTA
#define NT    64           // embeddings per chunk
#define NCHUNK (K_EMB / NT)
#define BLOCK 256
#define BUFB  (3 * 8192)   // bytes per B buffer (3 splits x 64x64 bf16)

#define DECAY 0.99f
#define ONE_MINUS_DECAY (1.0f - 0.99f)
#define EPSV 1e-5f

__device__ __forceinline__ uint32_t smem_u32(const void* p) {
    uint32_t a;
    asm("{ .reg .u64 t; cvta.to.shared.u64 t, %1; cvt.u32.u64 %0, t; }"
        : "=r"(a) : "l"(p));
    return a;
}

#define LDMATRIX_X4(r0, r1, r2, r3, addr) \
    asm volatile("ldmatrix.sync.aligned.m8n8.x4.shared.b16 {%0,%1,%2,%3}, [%4];" \
                 : "=r"(r0), "=r"(r1), "=r"(r2), "=r"(r3) : "r"(addr))

#define MMA_BF16(d, a0, a1, a2, a3, b0, b1) \
    asm volatile("mma.sync.aligned.m16n8k16.row.col.f32.bf16.bf16.f32 " \
                 "{%0,%1,%2,%3}, {%4,%5,%6,%7}, {%8,%9}, {%0,%1,%2,%3};" \
                 : "+f"((d)[0]), "+f"((d)[1]), "+f"((d)[2]), "+f"((d)[3]) \
                 : "r"(a0), "r"(a1), "r"(a2), "r"(a3), "r"(b0), "r"(b1))

#define CP_ASYNC16(dst, src) \
    asm volatile("cp.async.cg.shared.global [%0], [%1], 16;" \
                 :: "r"(dst), "l"(src) : "memory")
#define CP_COMMIT() asm volatile("cp.async.commit_group;" ::: "memory")
#define CP_WAIT1()  asm volatile("cp.async.wait_group 1;" ::: "memory")
#define CP_WAIT0()  asm volatile("cp.async.wait_group 0;" ::: "memory")

// -------- scratch (device globals) --------
__device__ float g_counts[K_EMB];
__device__ float g_embed_sum[K_EMB * D_DIM];
__device__ float g_enorm[K_EMB];
__device__ float g_loss_sum;
__device__ int   g_emax2_bits;
__device__ int   g_nflag;
__device__ int   g_flaglist[N_PTS];
__device__ __nv_bfloat16 g_eb[3][K_EMB * D_DIM];   // 3-way bf16 split of embeddings

// -------- zero: tiny init kernel --------
__global__ void zero_kernel() {
    g_loss_sum = 0.f;
    g_nflag = 0;
    g_emax2_bits = 0;
}

// -------- prep: zero scratch, ||e||^2 (+max), bf16 3-split --------
__global__ void prep_kernel(const float* __restrict__ emb) {
    int t = blockIdx.x * blockDim.x + threadIdx.x;   // 65536 threads
    if (t < K_EMB * D_DIM) {
        g_embed_sum[t] = 0.f;
        float v = emb[t];
        __nv_bfloat16 b1 = __float2bfloat16(v);
        float r1 = v - __bfloat162float(b1);
        __nv_bfloat16 b2 = __float2bfloat16(r1);
        float r2 = r1 - __bfloat162float(b2);
        g_eb[0][t] = b1; g_eb[1][t] = b2; g_eb[2][t] = __float2bfloat16(r2);
    }
    if (t < K_EMB) {
        g_counts[t] = 0.f;
        const float4* row = (const float4*)(emb + (size_t)t * D_DIM);
        float s = 0.f;
        #pragma unroll
        for (int q = 0; q < 16; q++) {
            float4 v = row[q];
            s += v.x * v.x + v.y * v.y + v.z * v.z + v.w * v.w;
        }
        g_enorm[t] = s;
        atomicMax(&g_emax2_bits, __float_as_int(s));  // positive floats: int order ok
    }
}

// -------- main: 6-product HMMA scores + tree argmin + cert + epilogue --------
#define SMEM_TOTAL (2 * BUFB + 512 + 512 + 512 + 512 + 1024)

__global__ __launch_bounds__(BLOCK, 2) void vq_main(
    const float* __restrict__ z, const float* __restrict__ emb,
    float* __restrict__ out_zq, float* __restrict__ out_idx)
{
    extern __shared__ __align__(16) unsigned char smem[];
    unsigned char* b_s    = smem;
    float*         enorm  = (float*)(smem + 2 * BUFB);
    int*           s_bidx = (int*)  (smem + 2 * BUFB + 512);
    float*         s_gap  = (float*)(smem + 2 * BUFB + 1024);
    float*         s_nz2  = (float*)(smem + 2 * BUFB + 1536);
    float*         sred   = (float*)(smem + 2 * BUFB + 2048);
    unsigned char* zb     = smem + BUFB;          // aliases buffer 1 (prologue only)

    const int t    = threadIdx.x;
    const int warp = t >> 5, lane = t & 31;
    const int g    = lane >> 2, tc = lane & 3;
    const int pt0  = blockIdx.x * MT;
    const uint32_t bs0    = smem_u32(b_s);
    const uint32_t enorm0 = smem_u32(enorm);

    auto stage = [&](int c, int buf) {
        #pragma unroll
        for (int r = 0; r < 6; r++) {
            int id = t + BLOCK * r;              // 0..1535 16B-units
            int sp = id >> 9;
            int rem = id & 511, rw = rem >> 3, u = rem & 7;
            const unsigned char* src = (const unsigned char*)g_eb[sp]
                                     + (size_t)c * 8192 + rw * 128 + u * 16;
            uint32_t dst = bs0 + buf * BUFB + sp * 8192 + rw * 128
                         + ((u ^ (rw & 7)) << 4);
            CP_ASYNC16(dst, src);
        }
        if (t < 16) {
            const unsigned char* src = (const unsigned char*)(g_enorm + c * NT) + t * 16;
            CP_ASYNC16(enorm0 + buf * 256 + t * 16, src);
        }
    };

    stage(0, 0);
    CP_COMMIT();

    // ======== A: z 3-split bf16 -> ldmatrix fragments; also ||z||^2 ========
    uint32_t afrag[3][4][4];   // [split][kstep][reg]
    {
        float v[32];
        const int row  = t >> 1;            // 0..127
        const int colh = (t & 1) * 32;      // column half
        {
            const float4* zg = (const float4*)(z + (size_t)(pt0 + row) * D_DIM + colh);
            #pragma unroll
            for (int q = 0; q < 8; q++) {
                float4 w = zg[q];
                v[4 * q] = w.x; v[4 * q + 1] = w.y; v[4 * q + 2] = w.z; v[4 * q + 3] = w.w;
            }
        }
        float nzp = 0.f;
        #pragma unroll
        for (int j = 0; j < 32; j++) nzp += v[j] * v[j];
        nzp += __shfl_xor_sync(0xffffffffu, nzp, 1);
        if ((t & 1) == 0) s_nz2[row] = nzp;

        const uint32_t zb0 = smem_u32(zb);
        #pragma unroll
        for (int s = 0; s < 3; s++) {
            #pragma unroll
            for (int u4 = 0; u4 < 4; u4++) {            // 4 uint4 units of 8 bf16
                uint32_t w[4];
                #pragma unroll
                for (int h = 0; h < 4; h++) {
                    int j = u4 * 8 + 2 * h;
                    __nv_bfloat16 b0 = __float2bfloat16(v[j]);
                    __nv_bfloat16 b1 = __float2bfloat16(v[j + 1]);
                    w[h] = ((uint32_t)__bfloat16_as_ushort(b1) << 16)
                         | (uint32_t)__bfloat16_as_ushort(b0);
                    v[j]     -= __bfloat162float(b0);
                    v[j + 1] -= __bfloat162float(b1);
                }
                int unit = (colh >> 3) + u4;             // 0..7
                *(uint4*)(zb + row * 128 + ((unit ^ (row & 7)) << 4)) =
                    make_uint4(w[0], w[1], w[2], w[3]);
            }
            __syncthreads();
            const int rl = warp * 16 + (lane & 15);
            #pragma unroll
            for (int ks = 0; ks < 4; ks++) {
                int unit = ks * 2 + (lane >> 4);
                uint32_t addr = zb0 + rl * 128 + ((unit ^ (rl & 7)) << 4);
                LDMATRIX_X4(afrag[s][ks][0], afrag[s][ks][1],
                            afrag[s][ks][2], afrag[s][ks][3], addr);
            }
            __syncthreads();
        }
    }

    float s1a = FLT_MAX, s2a = FLT_MAX, s1b = FLT_MAX, s2b = FLT_MAX;
    int   i1a = 0, i1b = 0;

    // exact (s1, s2, i1) merge with a per-chunk 16-score block
    auto upd = [&](float* m, int c, float& s1, float& s2, int& i1) {
        // parallel fminf tree (15 FMNMX, alu pipe, no FSETP chains)
        float u0 = fminf(m[0], m[8]),  u1 = fminf(m[1], m[9]);
        float u2 = fminf(m[2], m[10]), u3 = fminf(m[3], m[11]);
        float u4 = fminf(m[4], m[12]), u5 = fminf(m[5], m[13]);
        float u6 = fminf(m[6], m[14]), u7 = fminf(m[7], m[15]);
        float v0 = fminf(u0, u4), v1 = fminf(u1, u5);
        float v2 = fminf(u2, u6), v3 = fminf(u3, u7);
        float cmin = fminf(fminf(v0, v2), fminf(v1, v3));
        if (cmin < s1) {
            // rare slow path: recover index + in-chunk second
            float sec = FLT_MAX; int jb = -1;
            #pragma unroll
            for (int j = 0; j < 16; j++) {
                bool win = (m[j] == cmin) && (jb < 0);
                jb  = win ? j : jb;
                sec = win ? sec : fminf(sec, m[j]);
            }
            s2 = fminf(s1, sec);
            s1 = cmin;
            i1 = c * NT + ((jb >> 1) << 3) + 2 * tc + (jb & 1);
        } else {
            s2 = fminf(s2, cmin);
        }
    };

    for (int c = 0; c < NCHUNK; c++) {
        const int cur = c & 1;
        if (c + 1 < NCHUNK) {
            stage(c + 1, cur ^ 1);
            CP_COMMIT();
            CP_WAIT1();
        } else {
            CP_WAIT0();
        }
        __syncthreads();

        float acc[8][4];
        #pragma unroll
        for (int nt = 0; nt < 8; nt++)
            #pragma unroll
            for (int i = 0; i < 4; i++) acc[nt][i] = 0.f;

        // 6 products: b-split s consumed by a-splits 0..(2-s)
        #pragma unroll
        for (int s = 0; s < 3; s++) {
            const uint32_t bbase = bs0 + cur * BUFB + s * 8192;
            const int AUSE = 3 - s;
            #pragma unroll
            for (int kh = 0; kh < 2; kh++) {
                #pragma unroll
                for (int nt = 0; nt < 8; nt++) {
                    uint32_t b0, b1, b2, b3;
                    int rw = nt * 8 + (lane & 7);
                    int unit = kh * 4 + (lane >> 3);
                    uint32_t addr = bbase + rw * 128 + ((unit ^ (rw & 7)) << 4);
                    LDMATRIX_X4(b0, b1, b2, b3, addr);
                    #pragma unroll
                    for (int a = 0; a < 3; a++) {
                        if (a < AUSE) {
                            const uint32_t* af = afrag[a][kh * 2];
                            MMA_BF16(acc[nt], af[0], af[1], af[2], af[3], b0, b1);
                            af = afrag[a][kh * 2 + 1];
                            MMA_BF16(acc[nt], af[0], af[1], af[2], af[3], b2, b3);
                        }
                    }
                }
            }
        }

        // ---- scores (FFMA with imm -2) ----
        const float* en = enorm + cur * 64;
        float ma[16], mb[16];
        #pragma unroll
        for (int nt = 0; nt < 8; nt++) {
            float2 e2 = *(const float2*)(en + nt * 8 + 2 * tc);
            ma[2 * nt]     = fmaf(-2.f, acc[nt][0], e2.x);
            ma[2 * nt + 1] = fmaf(-2.f, acc[nt][1], e2.y);
            mb[2 * nt]     = fmaf(-2.f, acc[nt][2], e2.x);
            mb[2 * nt + 1] = fmaf(-2.f, acc[nt][3], e2.y);
        }
        upd(ma, c, s1a, s2a, i1a);
        upd(mb, c, s1b, s2b, i1b);
        __syncthreads();
    }

    // ---- quad reduction of (best, idx, second) ----
    #pragma unroll
    for (int off = 1; off <= 2; off <<= 1) {
        float o1 = __shfl_xor_sync(0xffffffffu, s1a, off);
        int   oi = __shfl_xor_sync(0xffffffffu, i1a, off);
        float o2 = __shfl_xor_sync(0xffffffffu, s2a, off);
        if (o1 < s1a || (o1 == s1a && oi < i1a)) { s2a = fminf(s1a, o2); s1a = o1; i1a = oi; }
        else                                     { s2a = fminf(s2a, o1); }
        o1 = __shfl_xor_sync(0xffffffffu, s1b, off);
        oi = __shfl_xor_sync(0xffffffffu, i1b, off);
        o2 = __shfl_xor_sync(0xffffffffu, s2b, off);
        if (o1 < s1b || (o1 == s1b && oi < i1b)) { s2b = fminf(s1b, o2); s1b = o1; i1b = oi; }
        else                                     { s2b = fminf(s2b, o1); }
    }
    if (tc == 0) {
        s_bidx[warp * 16 + g]     = i1a;  s_gap[warp * 16 + g]     = s2a - s1a;
        s_bidx[warp * 16 + g + 8] = i1b;  s_gap[warp * 16 + g + 8] = s2b - s1b;
    }
    __syncthreads();

    // ---- certification: 3-split dropped terms ~2^-27 -> tau has ~100x margin ----
    const float emax2 = __int_as_float(g_emax2_bits);
    if (t < MT) {
        float tau = 5e-6f * (s_nz2[t] + emax2);
        int b = s_bidx[t];
        if (s_gap[t] <= tau) {
            int slot = atomicAdd(&g_nflag, 1);
            g_flaglist[slot] = pt0 + t;
            s_bidx[t] = -1;
        } else {
            out_idx[pt0 + t] = (float)b;
            atomicAdd(&g_counts[b], 1.f);
        }
    }
    __syncthreads();

    // ---- epilogue for certified points ----
    float lsum = 0.f;
    #pragma unroll
    for (int r = 0; r < 8; r++) {
        int id = t + BLOCK * r;          // 128 pts x 16 float4-units
        int p = id >> 4, q = id & 15;
        int b = s_bidx[p];
        if (b >= 0) {
            int pt = pt0 + p;
            float4 qv = *(const float4*)(emb + (size_t)b * D_DIM + q * 4);
            float4 zv = *(const float4*)(z + (size_t)pt * D_DIM + q * 4);
            *(float4*)(out_zq + (size_t)pt * D_DIM + q * 4) = qv;
            float dx = zv.x - qv.x, dy = zv.y - qv.y;
            float dz2 = zv.z - qv.z, dw = zv.w - qv.w;
            lsum += dx * dx + dy * dy + dz2 * dz2 + dw * dw;
            float* esum = g_embed_sum + (size_t)b * D_DIM + q * 4;
            atomicAdd(esum + 0, zv.x);
            atomicAdd(esum + 1, zv.y);
            atomicAdd(esum + 2, zv.z);
            atomicAdd(esum + 3, zv.w);
        }
    }

    sred[t] = lsum;
    __syncthreads();
    for (int s = BLOCK / 2; s > 0; s >>= 1) {
        if (t < s) sred[t] += sred[t + s];
        __syncthreads();
    }
    if (t == 0) atomicAdd(&g_loss_sum, sred[0]);
}

// -------- fallback: warp-per-point exact fp32 argmin + epilogue --------
#define FB_BLOCKS 1024
__global__ __launch_bounds__(256) void fallback_kernel(
    const float* __restrict__ z, const float* __restrict__ emb,
    float* __restrict__ out_zq, float* __restrict__ out_idx)
{
    const int nflag = g_nflag;
    const int lane  = threadIdx.x & 31;
    const int gwarp = (blockIdx.x * 256 + threadIdx.x) >> 5;
    const int nwarp = (FB_BLOCKS * 256) >> 5;   // 8192 warps

    for (int i = gwarp; i < nflag; i += nwarp) {
        const int pt = g_flaglist[i];
        float4 zr[16];
        const float4* zg = (const float4*)(z + (size_t)pt * D_DIM);
        #pragma unroll
        for (int q = 0; q < 16; q++) zr[q] = zg[q];   // broadcast load

        float best = FLT_MAX; int bi = 0;
        for (int c = 0; c < 32; c++) {
            int e = c * 32 + lane;                    // lane-strided codes
            const float4* er = (const float4*)(emb + (size_t)e * D_DIM);
            float a0 = 0.f, a1 = 0.f, a2 = 0.f, a3 = 0.f;
            #pragma unroll
            for (int q = 0; q < 16; q++) {
                float4 ev = er[q];
                a0 = fmaf(ev.x, zr[q].x, a0);
                a1 = fmaf(ev.y, zr[q].y, a1);
                a2 = fmaf(ev.z, zr[q].z, a2);
                a3 = fmaf(ev.w, zr[q].w, a3);
            }
            float s = g_enorm[e] - 2.f * ((a0 + a1) + (a2 + a3));
            if (s < best) { best = s; bi = e; }
        }
        #pragma unroll
        for (int off = 16; off > 0; off >>= 1) {
            float s2 = __shfl_xor_sync(0xffffffffu, best, off);
            int   b2 = __shfl_xor_sync(0xffffffffu, bi, off);
            if (s2 < best || (s2 == best && b2 < bi)) { best = s2; bi = b2; }
        }

        float lsum = 0.f;
        if (lane < 16) {
            float4 qv = *(const float4*)(emb + (size_t)bi * D_DIM + lane * 4);
            float4 zv = zr[lane];
            *(float4*)(out_zq + (size_t)pt * D_DIM + lane * 4) = qv;
            float dx = zv.x - qv.x, dy = zv.y - qv.y;
            float dz2 = zv.z - qv.z, dw = zv.w - qv.w;
            lsum = dx * dx + dy * dy + dz2 * dz2 + dw * dw;
            float* esum = g_embed_sum + (size_t)bi * D_DIM + lane * 4;
            atomicAdd(esum + 0, zv.x);
            atomicAdd(esum + 1, zv.y);
            atomicAdd(esum + 2, zv.z);
            atomicAdd(esum + 3, zv.w);
        }
        #pragma unroll
        for (int off = 8; off > 0; off >>= 1)
            lsum += __shfl_xor_sync(0xffffffffu, lsum, off);
        if (lane == 0) {
            out_idx[pt] = (float)bi;
            atomicAdd(&g_counts[bi], 1.f);
            atomicAdd(&g_loss_sum, lsum);
        }
    }
}

// -------- finalize: EMA updates, normalization, loss mean --------
__global__ __launch_bounds__(1024) void finalize_kernel(
    const float* __restrict__ cluster_size, const float* __restrict__ ema,
    float* __restrict__ out_loss, float* __restrict__ out_nemb,
    float* __restrict__ out_ncs, float* __restrict__ out_nema)
{
    __shared__ float sred[1024];
    const int t = threadIdx.x;   // one CTA, 1024 threads (== K)

    float c = cluster_size[t] * DECAY + ONE_MINUS_DECAY * g_counts[t];
    out_ncs[t] = c;
    sred[t] = c;
    __syncthreads();
    for (int s = 512; s > 0; s >>= 1) {
        if (t < s) sred[t] += sred[t + s];
        __syncthreads();
    }
    float n = sred[0];
    float cs = (c + EPSV) / (n + (float)K_EMB * EPSV) * n;
    float inv = 1.f / cs;

    #pragma unroll 4
    for (int q = 0; q < D_DIM; q++) {
        int idx = t * D_DIM + q;
        float s = ema[idx] * DECAY + ONE_MINUS_DECAY * g_embed_sum[idx];
        out_nema[idx] = s;
        out_nemb[idx] = s * inv;
    }
    if (t == 0) out_loss[0] = g_loss_sum / (float)((size_t)N_PTS * D_DIM);
}

// -------- launch --------
extern "C" void kernel_launch(void* const* d_in, const int* in_sizes, int n_in,
                              void* d_out, int out_size) {
    const float* z   = (const float*)d_in[0];
    const float* emb = (const float*)d_in[1];
    const float* cs  = (const float*)d_in[2];
    const float* ema = (const float*)d_in[3];

    float* out      = (float*)d_out;
    float* out_zq   = out;                               // N*D
    float* out_loss = out + (size_t)N_PTS * D_DIM;       // 1
    float* out_idx  = out_loss + 1;                      // N
    float* out_nemb = out_idx + N_PTS;                   // K*D
    float* out_ncs  = out_nemb + (size_t)K_EMB * D_DIM;  // K
    float* out_nema = out_ncs + K_EMB;                   // K*D

    cudaFuncSetAttribute(vq_main, cudaFuncAttributeMaxDynamicSharedMemorySize,
                         SMEM_TOTAL);

    zero_kernel<<<1, 1>>>();
    prep_kernel<<<256, 256>>>(emb);
    vq_main<<<N_PTS / MT, BLOCK, SMEM_TOTAL>>>(z, emb, out_zq, out_idx);
    fallback_kernel<<<FB_BLOCKS, 256>>>(z, emb, out_zq, out_idx);
    finalize_kernel<<<1, 1024>>>(cs, ema, out_loss, out_nemb, out_ncs, out_nema);
}

// round 15
// speedup vs baseline: 1.3843x; 1.3843x over previous
#include <cuda_runtime.h>
#include <cuda_bf16.h>
#include <float.h>
#include <cstdint>

#define N_PTS 131072
#define K_EMB 1024
#define D_DIM 64
#define MT    128          // points per CTA
#define NT    128          // embeddings per chunk (2 n-halves of 64)
#define NCHUNK (K_EMB / NT)
#define BLOCK 256
#define BUFB  (2 * 16384)  // bytes per B buffer (2 splits x 128x64 bf16)

#define DECAY 0.99f
#define ONE_MINUS_DECAY (1.0f - 0.99f)
#define EPSV 1e-5f

__device__ __forceinline__ uint32_t smem_u32(const void* p) {
    uint32_t a;
    asm("{ .reg .u64 t; cvta.to.shared.u64 t, %1; cvt.u32.u64 %0, t; }"
        : "=r"(a) : "l"(p));
    return a;
}

#define LDMATRIX_X4(r0, r1, r2, r3, addr) \
    asm volatile("ldmatrix.sync.aligned.m8n8.x4.shared.b16 {%0,%1,%2,%3}, [%4];" \
                 : "=r"(r0), "=r"(r1), "=r"(r2), "=r"(r3) : "r"(addr))

#define MMA_BF16(d, a0, a1, a2, a3, b0, b1) \
    asm volatile("mma.sync.aligned.m16n8k16.row.col.f32.bf16.bf16.f32 " \
                 "{%0,%1,%2,%3}, {%4,%5,%6,%7}, {%8,%9}, {%0,%1,%2,%3};" \
                 : "+f"((d)[0]), "+f"((d)[1]), "+f"((d)[2]), "+f"((d)[3]) \
                 : "r"(a0), "r"(a1), "r"(a2), "r"(a3), "r"(b0), "r"(b1))

#define CP_ASYNC16(dst, src) \
    asm volatile("cp.async.cg.shared.global [%0], [%1], 16;" \
                 :: "r"(dst), "l"(src) : "memory")
#define CP_COMMIT() asm volatile("cp.async.commit_group;" ::: "memory")
#define CP_WAIT1()  asm volatile("cp.async.wait_group 1;" ::: "memory")
#define CP_WAIT0()  asm volatile("cp.async.wait_group 0;" ::: "memory")

// -------- scratch (device globals) --------
__device__ float g_counts[K_EMB];
__device__ float g_embed_sum[K_EMB * D_DIM];
__device__ float g_enorm[K_EMB];
__device__ float g_loss_sum;
__device__ int   g_emax2_bits;
__device__ int   g_nflag;
__device__ int   g_flaglist[N_PTS];
__device__ __nv_bfloat16 g_eb[2][K_EMB * D_DIM];   // 2-way bf16 split of embeddings

// -------- zero: tiny init kernel --------
__global__ void zero_kernel() {
    g_loss_sum = 0.f;
    g_nflag = 0;
    g_emax2_bits = 0;
}

// -------- prep: zero scratch, ||e||^2 (+max), bf16 2-split --------
__global__ void prep_kernel(const float* __restrict__ emb) {
    int t = blockIdx.x * blockDim.x + threadIdx.x;   // 65536 threads
    if (t < K_EMB * D_DIM) {
        g_embed_sum[t] = 0.f;
        float v = emb[t];
        __nv_bfloat16 b1 = __float2bfloat16(v);
        float r1 = v - __bfloat162float(b1);
        g_eb[0][t] = b1; g_eb[1][t] = __float2bfloat16(r1);
    }
    if (t < K_EMB) {
        g_counts[t] = 0.f;
        const float4* row = (const float4*)(emb + (size_t)t * D_DIM);
        float s = 0.f;
        #pragma unroll
        for (int q = 0; q < 16; q++) {
            float4 v = row[q];
            s += v.x * v.x + v.y * v.y + v.z * v.z + v.w * v.w;
        }
        g_enorm[t] = s;
        atomicMax(&g_emax2_bits, __float_as_int(s));  // positive floats: int order ok
    }
}

// -------- main: 3-product HMMA scores + cert + epilogue (NT=128 chunks) --------
// smem: [0, 2*BUFB) B double buffer | +1024 enorm(2x128f) | +512 s_bidx |
//       +512 s_gap | +512 s_nz2 | +1024 sred
#define SMEM_TOTAL (2 * BUFB + 1024 + 512 + 512 + 512 + 1024)

__global__ __launch_bounds__(BLOCK, 2) void vq_main(
    const float* __restrict__ z, const float* __restrict__ emb,
    float* __restrict__ out_zq, float* __restrict__ out_idx)
{
    extern __shared__ __align__(16) unsigned char smem[];
    unsigned char* b_s    = smem;
    float*         enorm  = (float*)(smem + 2 * BUFB);
    int*           s_bidx = (int*)  (smem + 2 * BUFB + 1024);
    float*         s_gap  = (float*)(smem + 2 * BUFB + 1536);
    float*         s_nz2  = (float*)(smem + 2 * BUFB + 2048);
    float*         sred   = (float*)(smem + 2 * BUFB + 2560);
    unsigned char* zb     = smem + BUFB;          // aliases buffer 1 (prologue only)

    const int t    = threadIdx.x;
    const int warp = t >> 5, lane = t & 31;
    const int g    = lane >> 2, tc = lane & 3;
    const int pt0  = blockIdx.x * MT;
    const uint32_t bs0    = smem_u32(b_s);
    const uint32_t enorm0 = smem_u32(enorm);

    // stage chunk c (128 codes, 2 splits) into buffer buf
    auto stage = [&](int c, int buf) {
        #pragma unroll
        for (int r = 0; r < 8; r++) {
            int id = t + BLOCK * r;              // 0..2047 16B-units
            int sp = id >> 10;
            int rem = id & 1023, rw = rem >> 3, u = rem & 7;
            const unsigned char* src = (const unsigned char*)g_eb[sp]
                                     + (size_t)c * 16384 + rw * 128 + u * 16;
            uint32_t dst = bs0 + buf * BUFB + sp * 16384 + rw * 128
                         + ((u ^ (rw & 7)) << 4);
            CP_ASYNC16(dst, src);
        }
        if (t < 32) {
            const unsigned char* src = (const unsigned char*)(g_enorm + c * NT) + t * 16;
            CP_ASYNC16(enorm0 + buf * 512 + t * 16, src);
        }
    };

    stage(0, 0);
    CP_COMMIT();

    // ======== A: z 2-split bf16 -> ldmatrix fragments; also ||z||^2 ========
    uint32_t afrag[2][4][4];   // [split][kstep][reg]
    {
        float v[32];
        const int row  = t >> 1;            // 0..127
        const int colh = (t & 1) * 32;      // column half
        {
            const float4* zg = (const float4*)(z + (size_t)(pt0 + row) * D_DIM + colh);
            #pragma unroll
            for (int q = 0; q < 8; q++) {
                float4 w = zg[q];
                v[4 * q] = w.x; v[4 * q + 1] = w.y; v[4 * q + 2] = w.z; v[4 * q + 3] = w.w;
            }
        }
        float nzp = 0.f;
        #pragma unroll
        for (int j = 0; j < 32; j++) nzp += v[j] * v[j];
        nzp += __shfl_xor_sync(0xffffffffu, nzp, 1);
        if ((t & 1) == 0) s_nz2[row] = nzp;

        const uint32_t zb0 = smem_u32(zb);
        #pragma unroll
        for (int s = 0; s < 2; s++) {
            #pragma unroll
            for (int u4 = 0; u4 < 4; u4++) {            // 4 uint4 units of 8 bf16
                uint32_t w[4];
                #pragma unroll
                for (int h = 0; h < 4; h++) {
                    int j = u4 * 8 + 2 * h;
                    __nv_bfloat16 b0 = __float2bfloat16(v[j]);
                    __nv_bfloat16 b1 = __float2bfloat16(v[j + 1]);
                    w[h] = ((uint32_t)__bfloat16_as_ushort(b1) << 16)
                         | (uint32_t)__bfloat16_as_ushort(b0);
                    v[j]     -= __bfloat162float(b0);
                    v[j + 1] -= __bfloat162float(b1);
                }
                int unit = (colh >> 3) + u4;             // 0..7
                *(uint4*)(zb + row * 128 + ((unit ^ (row & 7)) << 4)) =
                    make_uint4(w[0], w[1], w[2], w[3]);
            }
            __syncthreads();
            const int rl = warp * 16 + (lane & 15);
            #pragma unroll
            for (int ks = 0; ks < 4; ks++) {
                int unit = ks * 2 + (lane >> 4);
                uint32_t addr = zb0 + rl * 128 + ((unit ^ (rl & 7)) << 4);
                LDMATRIX_X4(afrag[s][ks][0], afrag[s][ks][1],
                            afrag[s][ks][2], afrag[s][ks][3], addr);
            }
            __syncthreads();
        }
    }

    float s1a = FLT_MAX, s2a = FLT_MAX, s1b = FLT_MAX, s2b = FLT_MAX;
    int   i1a = 0, i1b = 0;

    for (int c = 0; c < NCHUNK; c++) {
        const int cur = c & 1;
        if (c + 1 < NCHUNK) {
            stage(c + 1, cur ^ 1);
            CP_COMMIT();
            CP_WAIT1();
        } else {
            CP_WAIT0();
        }
        __syncthreads();

        // two n-halves of 64 codes each, reusing acc registers
        #pragma unroll
        for (int nh = 0; nh < 2; nh++) {
            float acc[8][4];
            #pragma unroll
            for (int nt = 0; nt < 8; nt++)
                #pragma unroll
                for (int i = 0; i < 4; i++) acc[nt][i] = 0.f;

            // products: a1b1, a2b1 (b-split 0), a1b2 (b-split 1)
            #pragma unroll
            for (int s = 0; s < 2; s++) {
                const uint32_t bbase = bs0 + cur * BUFB + s * 16384;
                #pragma unroll
                for (int kh = 0; kh < 2; kh++) {
                    #pragma unroll
                    for (int nt = 0; nt < 8; nt++) {
                        uint32_t b0, b1, b2, b3;
                        int rw = nh * 64 + nt * 8 + (lane & 7);
                        int unit = kh * 4 + (lane >> 3);
                        uint32_t addr = bbase + rw * 128 + ((unit ^ (rw & 7)) << 4);
                        LDMATRIX_X4(b0, b1, b2, b3, addr);
                        {
                            const uint32_t* af = afrag[0][kh * 2];
                            MMA_BF16(acc[nt], af[0], af[1], af[2], af[3], b0, b1);
                        }
                        {
                            const uint32_t* af = afrag[0][kh * 2 + 1];
                            MMA_BF16(acc[nt], af[0], af[1], af[2], af[3], b2, b3);
                        }
                        if (s == 0) {
                            const uint32_t* af = afrag[1][kh * 2];
                            MMA_BF16(acc[nt], af[0], af[1], af[2], af[3], b0, b1);
                            af = afrag[1][kh * 2 + 1];
                            MMA_BF16(acc[nt], af[0], af[1], af[2], af[3], b2, b3);
                        }
                    }
                }
            }

            // ---- scores + running best/second ----
            const float* en = enorm + cur * 128 + nh * 64;
            #pragma unroll
            for (int nt = 0; nt < 8; nt++) {
                int nl = nt * 8 + 2 * tc;
                int n0 = c * NT + nh * 64 + nl;
                float e0 = en[nl], e1 = en[nl + 1];
                float s00 = fmaf(-2.f, acc[nt][0], e0);
                float s01 = fmaf(-2.f, acc[nt][1], e1);
                float s10 = fmaf(-2.f, acc[nt][2], e0);
                float s11 = fmaf(-2.f, acc[nt][3], e1);
                if (s00 < s1a) { s2a = s1a; s1a = s00; i1a = n0; } else s2a = fminf(s2a, s00);
                if (s01 < s1a) { s2a = s1a; s1a = s01; i1a = n0 + 1; } else s2a = fminf(s2a, s01);
                if (s10 < s1b) { s2b = s1b; s1b = s10; i1b = n0; } else s2b = fminf(s2b, s10);
                if (s11 < s1b) { s2b = s1b; s1b = s11; i1b = n0 + 1; } else s2b = fminf(s2b, s11);
            }
        }
        __syncthreads();
    }

    // ---- quad reduction of (best, idx, second) ----
    #pragma unroll
    for (int off = 1; off <= 2; off <<= 1) {
        float o1 = __shfl_xor_sync(0xffffffffu, s1a, off);
        int   oi = __shfl_xor_sync(0xffffffffu, i1a, off);
        float o2 = __shfl_xor_sync(0xffffffffu, s2a, off);
        if (o1 < s1a || (o1 == s1a && oi < i1a)) { s2a = fminf(s1a, o2); s1a = o1; i1a = oi; }
        else                                     { s2a = fminf(s2a, o1); }
        o1 = __shfl_xor_sync(0xffffffffu, s1b, off);
        oi = __shfl_xor_sync(0xffffffffu, i1b, off);
        o2 = __shfl_xor_sync(0xffffffffu, s2b, off);
        if (o1 < s1b || (o1 == s1b && oi < i1b)) { s2b = fminf(s1b, o2); s1b = o1; i1b = oi; }
        else                                     { s2b = fminf(s2b, o1); }
    }
    if (tc == 0) {
        s_bidx[warp * 16 + g]     = i1a;  s_gap[warp * 16 + g]     = s2a - s1a;
        s_bidx[warp * 16 + g + 8] = i1b;  s_gap[warp * 16 + g + 8] = s2b - s1b;
    }
    __syncthreads();

    // ---- certification: flag uncertain points for exact fallback ----
    const float emax2 = __int_as_float(g_emax2_bits);
    if (t < MT) {
        float tau = 3.1e-5f * (s_nz2[t] + emax2);
        int b = s_bidx[t];
        if (s_gap[t] <= tau) {
            int slot = atomicAdd(&g_nflag, 1);
            g_flaglist[slot] = pt0 + t;
            s_bidx[t] = -1;
        } else {
            out_idx[pt0 + t] = (float)b;
            atomicAdd(&g_counts[b], 1.f);
        }
    }
    __syncthreads();

    // ---- epilogue for certified points ----
    float lsum = 0.f;
    #pragma unroll
    for (int r = 0; r < 8; r++) {
        int id = t + BLOCK * r;          // 128 pts x 16 float4-units
        int p = id >> 4, q = id & 15;
        int b = s_bidx[p];
        if (b >= 0) {
            int pt = pt0 + p;
            float4 qv = *(const float4*)(emb + (size_t)b * D_DIM + q * 4);
            float4 zv = *(const float4*)(z + (size_t)pt * D_DIM + q * 4);
            *(float4*)(out_zq + (size_t)pt * D_DIM + q * 4) = qv;
            float dx = zv.x - qv.x, dy = zv.y - qv.y;
            float dz2 = zv.z - qv.z, dw = zv.w - qv.w;
            lsum += dx * dx + dy * dy + dz2 * dz2 + dw * dw;
            float* esum = g_embed_sum + (size_t)b * D_DIM + q * 4;
            atomicAdd(esum + 0, zv.x);
            atomicAdd(esum + 1, zv.y);
            atomicAdd(esum + 2, zv.z);
            atomicAdd(esum + 3, zv.w);
        }
    }

    sred[t] = lsum;
    __syncthreads();
    for (int s = BLOCK / 2; s > 0; s >>= 1) {
        if (t < s) sred[t] += sred[t + s];
        __syncthreads();
    }
    if (t == 0) atomicAdd(&g_loss_sum, sred[0]);
}

// -------- fallback: BLOCK-per-point exact fp32 argmin (short critical path) --------
#define FB_BLOCKS 2048
__global__ __launch_bounds__(256) void fallback_kernel(
    const float* __restrict__ z, const float* __restrict__ emb,
    float* __restrict__ out_zq, float* __restrict__ out_idx)
{
    __shared__ float zs[D_DIM];
    __shared__ float wbest[8];
    __shared__ int   wbidx[8];

    const int nflag = g_nflag;
    const int t = threadIdx.x, lane = t & 31, warp = t >> 5;

    for (int i = blockIdx.x; i < nflag; i += FB_BLOCKS) {
        const int pt = g_flaglist[i];
        if (t < 16) ((float4*)zs)[t] = ((const float4*)(z + (size_t)pt * D_DIM))[t];
        __syncthreads();

        float best = FLT_MAX; int bi = 0x7fffffff;
        #pragma unroll
        for (int c = 0; c < 4; c++) {           // thread t owns codes c*256 + t
            int e = c * 256 + t;
            const float4* er = (const float4*)(emb + (size_t)e * D_DIM);
            float a0 = 0.f, a1 = 0.f, a2 = 0.f, a3 = 0.f;
            #pragma unroll
            for (int q = 0; q < 16; q++) {
                float4 ev = er[q];
                a0 = fmaf(ev.x, zs[4 * q + 0], a0);
                a1 = fmaf(ev.y, zs[4 * q + 1], a1);
                a2 = fmaf(ev.z, zs[4 * q + 2], a2);
                a3 = fmaf(ev.w, zs[4 * q + 3], a3);
            }
            float s = g_enorm[e] - 2.f * ((a0 + a1) + (a2 + a3));
            if (s < best || (s == best && e < bi)) { best = s; bi = e; }
        }
        #pragma unroll
        for (int off = 16; off > 0; off >>= 1) {
            float s2 = __shfl_xor_sync(0xffffffffu, best, off);
            int   b2 = __shfl_xor_sync(0xffffffffu, bi, off);
            if (s2 < best || (s2 == best && b2 < bi)) { best = s2; bi = b2; }
        }
        if (lane == 0) { wbest[warp] = best; wbidx[warp] = bi; }
        __syncthreads();
        if (warp == 0) {
            best = (lane < 8) ? wbest[lane] : FLT_MAX;
            bi   = (lane < 8) ? wbidx[lane] : 0x7fffffff;
            #pragma unroll
            for (int off = 4; off > 0; off >>= 1) {
                float s2 = __shfl_xor_sync(0xffffffffu, best, off);
                int   b2 = __shfl_xor_sync(0xffffffffu, bi, off);
                if (s2 < best || (s2 == best && b2 < bi)) { best = s2; bi = b2; }
            }
            if (lane == 0) { wbidx[0] = bi; }
        }
        __syncthreads();
        bi = wbidx[0];

        // cooperative epilogue (threads 0..15 = warp 0 lanes 0..15)
        float lsum = 0.f;
        if (t < 16) {
            float4 qv = *(const float4*)(emb + (size_t)bi * D_DIM + t * 4);
            float4 zv = ((const float4*)zs)[t];
            *(float4*)(out_zq + (size_t)pt * D_DIM + t * 4) = qv;
            float dx = zv.x - qv.x, dy = zv.y - qv.y;
            float dz2 = zv.z - qv.z, dw = zv.w - qv.w;
            lsum = dx * dx + dy * dy + dz2 * dz2 + dw * dw;
            float* esum = g_embed_sum + (size_t)bi * D_DIM + t * 4;
            atomicAdd(esum + 0, zv.x);
            atomicAdd(esum + 1, zv.y);
            atomicAdd(esum + 2, zv.z);
            atomicAdd(esum + 3, zv.w);
        }
        if (warp == 0) {
            #pragma unroll
            for (int off = 16; off > 0; off >>= 1)
                lsum += __shfl_xor_sync(0xffffffffu, lsum, off);
            if (lane == 0) {
                out_idx[pt] = (float)bi;
                atomicAdd(&g_counts[bi], 1.f);
                atomicAdd(&g_loss_sum, lsum);
            }
        }
        __syncthreads();   // zs/wbest reuse next iteration
    }
}

// -------- finalize: EMA updates, normalization, loss mean --------
__global__ __launch_bounds__(1024) void finalize_kernel(
    const float* __restrict__ cluster_size, const float* __restrict__ ema,
    float* __restrict__ out_loss, float* __restrict__ out_nemb,
    float* __restrict__ out_ncs, float* __restrict__ out_nema)
{
    __shared__ float sred[1024];
    const int t = threadIdx.x;   // one CTA, 1024 threads (== K)

    float c = cluster_size[t] * DECAY + ONE_MINUS_DECAY * g_counts[t];
    out_ncs[t] = c;
    sred[t] = c;
    __syncthreads();
    for (int s = 512; s > 0; s >>= 1) {
        if (t < s) sred[t] += sred[t + s];
        __syncthreads();
    }
    float n = sred[0];
    float cs = (c + EPSV) / (n + (float)K_EMB * EPSV) * n;
    float inv = 1.f / cs;

    #pragma unroll 4
    for (int q = 0; q < D_DIM; q++) {
        int idx = t * D_DIM + q;
        float s = ema[idx] * DECAY + ONE_MINUS_DECAY * g_embed_sum[idx];
        out_nema[idx] = s;
        out_nemb[idx] = s * inv;
    }
    if (t == 0) out_loss[0] = g_loss_sum / (float)((size_t)N_PTS * D_DIM);
}

// -------- launch --------
extern "C" void kernel_launch(void* const* d_in, const int* in_sizes, int n_in,
                              void* d_out, int out_size) {
    const float* z   = (const float*)d_in[0];
    const float* emb = (const float*)d_in[1];
    const float* cs  = (const float*)d_in[2];
    const float* ema = (const float*)d_in[3];

    float* out      = (float*)d_out;
    float* out_zq   = out;                               // N*D
    float* out_loss = out + (size_t)N_PTS * D_DIM;       // 1
    float* out_idx  = out_loss + 1;                      // N
    float* out_nemb = out_idx + N_PTS;                   // K*D
    float* out_ncs  = out_nemb + (size_t)K_EMB * D_DIM;  // K
    float* out_nema = out_ncs + K_EMB;                   // K*D

    cudaFuncSetAttribute(vq_main, cudaFuncAttributeMaxDynamicSharedMemorySize,
                         SMEM_TOTAL);

    zero_kernel<<<1, 1>>>();
    prep_kernel<<<256, 256>>>(emb);
    vq_main<<<N_PTS / MT, BLOCK, SMEM_TOTAL>>>(z, emb, out_zq, out_idx);
    fallback_kernel<<<FB_BLOCKS, 256>>>(z, emb, out_zq, out_idx);
    finalize_kernel<<<1, 1024>>>(cs, ema, out_loss, out_nemb, out_ncs, out_nema);
}

// round 17
// speedup vs baseline: 2.7649x; 1.9973x over previous
#include <cuda_runtime.h>
#include <cuda_bf16.h>
#include <float.h>
#include <cstdint>

#define N_PTS 131072
#define K_EMB 1024
#define D_DIM 64
#define MT    128          // points per CTA
#define NT    128          // embeddings per chunk (2 n-halves of 64)
#define NCHUNK (K_EMB / NT)
#define BLOCK 256
#define BUFB  (2 * 16384)  // bytes per B buffer (2 splits x 128x64 bf16)

#define DECAY 0.99f
#define ONE_MINUS_DECAY (1.0f - 0.99f)
#define EPSV 1e-5f

__device__ __forceinline__ uint32_t smem_u32(const void* p) {
    uint32_t a;
    asm("{ .reg .u64 t; cvta.to.shared.u64 t, %1; cvt.u32.u64 %0, t; }"
        : "=r"(a) : "l"(p));
    return a;
}

#define LDMATRIX_X4(r0, r1, r2, r3, addr) \
    asm volatile("ldmatrix.sync.aligned.m8n8.x4.shared.b16 {%0,%1,%2,%3}, [%4];" \
                 : "=r"(r0), "=r"(r1), "=r"(r2), "=r"(r3) : "r"(addr))

#define MMA_BF16(d, a0, a1, a2, a3, b0, b1) \
    asm volatile("mma.sync.aligned.m16n8k16.row.col.f32.bf16.bf16.f32 " \
                 "{%0,%1,%2,%3}, {%4,%5,%6,%7}, {%8,%9}, {%0,%1,%2,%3};" \
                 : "+f"((d)[0]), "+f"((d)[1]), "+f"((d)[2]), "+f"((d)[3]) \
                 : "r"(a0), "r"(a1), "r"(a2), "r"(a3), "r"(b0), "r"(b1))

#define CP_ASYNC16(dst, src) \
    asm volatile("cp.async.cg.shared.global [%0], [%1], 16;" \
                 :: "r"(dst), "l"(src) : "memory")
#define CP_COMMIT() asm volatile("cp.async.commit_group;" ::: "memory")
#define CP_WAIT1()  asm volatile("cp.async.wait_group 1;" ::: "memory")
#define CP_WAIT0()  asm volatile("cp.async.wait_group 0;" ::: "memory")

// -------- scratch (device globals) --------
__device__ float g_counts[K_EMB];
__device__ float g_embed_sum[K_EMB * D_DIM];
__device__ float g_enorm[K_EMB];
__device__ float g_inv[K_EMB];
__device__ float g_loss_sum;
__device__ int   g_emax2_bits;
__device__ int   g_nflag;
__device__ int   g_flaglist[N_PTS];
__device__ __nv_bfloat16 g_eb[2][K_EMB * D_DIM];   // 2-way bf16 split of embeddings

// -------- zero: tiny init kernel --------
__global__ void zero_kernel() {
    g_loss_sum = 0.f;
    g_nflag = 0;
    g_emax2_bits = 0;
}

// -------- dummy: launch-index padding so vq_main lands at index 3 for ncu --------
__global__ void dummy_kernel() {}

// -------- prep: zero scratch, ||e||^2 (+max), bf16 2-split --------
__global__ void prep_kernel(const float* __restrict__ emb) {
    int t = blockIdx.x * blockDim.x + threadIdx.x;   // 65536 threads
    if (t < K_EMB * D_DIM) {
        g_embed_sum[t] = 0.f;
        float v = emb[t];
        __nv_bfloat16 b1 = __float2bfloat16(v);
        float r1 = v - __bfloat162float(b1);
        g_eb[0][t] = b1; g_eb[1][t] = __float2bfloat16(r1);
    }
    if (t < K_EMB) {
        g_counts[t] = 0.f;
        const float4* row = (const float4*)(emb + (size_t)t * D_DIM);
        float s = 0.f;
        #pragma unroll
        for (int q = 0; q < 16; q++) {
            float4 v = row[q];
            s += v.x * v.x + v.y * v.y + v.z * v.z + v.w * v.w;
        }
        g_enorm[t] = s;
        atomicMax(&g_emax2_bits, __float_as_int(s));  // positive floats: int order ok
    }
}

// -------- main: 3-product HMMA scores + cert + epilogue (NT=128 chunks) --------
#define SMEM_TOTAL (2 * BUFB + 1024 + 512 + 512 + 512 + 1024)

__global__ __launch_bounds__(BLOCK, 2) void vq_main(
    const float* __restrict__ z, const float* __restrict__ emb,
    float* __restrict__ out_zq, float* __restrict__ out_idx)
{
    extern __shared__ __align__(16) unsigned char smem[];
    unsigned char* b_s    = smem;
    float*         enorm  = (float*)(smem + 2 * BUFB);
    int*           s_bidx = (int*)  (smem + 2 * BUFB + 1024);
    float*         s_gap  = (float*)(smem + 2 * BUFB + 1536);
    float*         s_nz2  = (float*)(smem + 2 * BUFB + 2048);
    float*         sred   = (float*)(smem + 2 * BUFB + 2560);
    unsigned char* zb     = smem + BUFB;          // aliases buffer 1 (prologue only)

    const int t    = threadIdx.x;
    const int warp = t >> 5, lane = t & 31;
    const int g    = lane >> 2, tc = lane & 3;
    const int pt0  = blockIdx.x * MT;
    const uint32_t bs0    = smem_u32(b_s);
    const uint32_t enorm0 = smem_u32(enorm);

    // stage chunk c (128 codes, 2 splits) into buffer buf
    auto stage = [&](int c, int buf) {
        #pragma unroll
        for (int r = 0; r < 8; r++) {
            int id = t + BLOCK * r;              // 0..2047 16B-units
            int sp = id >> 10;
            int rem = id & 1023, rw = rem >> 3, u = rem & 7;
            const unsigned char* src = (const unsigned char*)g_eb[sp]
                                     + (size_t)c * 16384 + rw * 128 + u * 16;
            uint32_t dst = bs0 + buf * BUFB + sp * 16384 + rw * 128
                         + ((u ^ (rw & 7)) << 4);
            CP_ASYNC16(dst, src);
        }
        if (t < 32) {
            const unsigned char* src = (const unsigned char*)(g_enorm + c * NT) + t * 16;
            CP_ASYNC16(enorm0 + buf * 512 + t * 16, src);
        }
    };

    stage(0, 0);
    CP_COMMIT();

    // ======== A: z 2-split bf16 -> ldmatrix fragments; also ||z||^2 ========
    uint32_t afrag[2][4][4];   // [split][kstep][reg]
    {
        float v[32];
        const int row  = t >> 1;            // 0..127
        const int colh = (t & 1) * 32;      // column half
        {
            const float4* zg = (const float4*)(z + (size_t)(pt0 + row) * D_DIM + colh);
            #pragma unroll
            for (int q = 0; q < 8; q++) {
                float4 w = zg[q];
                v[4 * q] = w.x; v[4 * q + 1] = w.y; v[4 * q + 2] = w.z; v[4 * q + 3] = w.w;
            }
        }
        float nzp = 0.f;
        #pragma unroll
        for (int j = 0; j < 32; j++) nzp += v[j] * v[j];
        nzp += __shfl_xor_sync(0xffffffffu, nzp, 1);
        if ((t & 1) == 0) s_nz2[row] = nzp;

        const uint32_t zb0 = smem_u32(zb);
        #pragma unroll
        for (int s = 0; s < 2; s++) {
            #pragma unroll
            for (int u4 = 0; u4 < 4; u4++) {            // 4 uint4 units of 8 bf16
                uint32_t w[4];
                #pragma unroll
                for (int h = 0; h < 4; h++) {
                    int j = u4 * 8 + 2 * h;
                    __nv_bfloat16 b0 = __float2bfloat16(v[j]);
                    __nv_bfloat16 b1 = __float2bfloat16(v[j + 1]);
                    w[h] = ((uint32_t)__bfloat16_as_ushort(b1) << 16)
                         | (uint32_t)__bfloat16_as_ushort(b0);
                    v[j]     -= __bfloat162float(b0);
                    v[j + 1] -= __bfloat162float(b1);
                }
                int unit = (colh >> 3) + u4;             // 0..7
                *(uint4*)(zb + row * 128 + ((unit ^ (row & 7)) << 4)) =
                    make_uint4(w[0], w[1], w[2], w[3]);
            }
            __syncthreads();
            const int rl = warp * 16 + (lane & 15);
            #pragma unroll
            for (int ks = 0; ks < 4; ks++) {
                int unit = ks * 2 + (lane >> 4);
                uint32_t addr = zb0 + rl * 128 + ((unit ^ (rl & 7)) << 4);
                LDMATRIX_X4(afrag[s][ks][0], afrag[s][ks][1],
                            afrag[s][ks][2], afrag[s][ks][3], addr);
            }
            __syncthreads();
        }
    }

    float s1a = FLT_MAX, s2a = FLT_MAX, s1b = FLT_MAX, s2b = FLT_MAX;
    int   i1a = 0, i1b = 0;

    for (int c = 0; c < NCHUNK; c++) {
        const int cur = c & 1;
        if (c + 1 < NCHUNK) {
            stage(c + 1, cur ^ 1);
            CP_COMMIT();
            CP_WAIT1();
        } else {
            CP_WAIT0();
        }
        __syncthreads();

        // two n-halves of 64 codes each, reusing acc registers
        #pragma unroll
        for (int nh = 0; nh < 2; nh++) {
            float acc[8][4];
            #pragma unroll
            for (int nt = 0; nt < 8; nt++)
                #pragma unroll
                for (int i = 0; i < 4; i++) acc[nt][i] = 0.f;

            // products: a1b1, a2b1 (b-split 0), a1b2 (b-split 1)
            #pragma unroll
            for (int s = 0; s < 2; s++) {
                const uint32_t bbase = bs0 + cur * BUFB + s * 16384;
                #pragma unroll
                for (int kh = 0; kh < 2; kh++) {
                    #pragma unroll
                    for (int nt = 0; nt < 8; nt++) {
                        uint32_t b0, b1, b2, b3;
                        int rw = nh * 64 + nt * 8 + (lane & 7);
                        int unit = kh * 4 + (lane >> 3);
                        uint32_t addr = bbase + rw * 128 + ((unit ^ (rw & 7)) << 4);
                        LDMATRIX_X4(b0, b1, b2, b3, addr);
                        {
                            const uint32_t* af = afrag[0][kh * 2];
                            MMA_BF16(acc[nt], af[0], af[1], af[2], af[3], b0, b1);
                        }
                        {
                            const uint32_t* af = afrag[0][kh * 2 + 1];
                            MMA_BF16(acc[nt], af[0], af[1], af[2], af[3], b2, b3);
                        }
                        if (s == 0) {
                            const uint32_t* af = afrag[1][kh * 2];
                            MMA_BF16(acc[nt], af[0], af[1], af[2], af[3], b0, b1);
                            af = afrag[1][kh * 2 + 1];
                            MMA_BF16(acc[nt], af[0], af[1], af[2], af[3], b2, b3);
                        }
                    }
                }
            }

            // ---- scores + running best/second ----
            const float* en = enorm + cur * 128 + nh * 64;
            #pragma unroll
            for (int nt = 0; nt < 8; nt++) {
                int nl = nt * 8 + 2 * tc;
                int n0 = c * NT + nh * 64 + nl;
                float e0 = en[nl], e1 = en[nl + 1];
                float s00 = fmaf(-2.f, acc[nt][0], e0);
                float s01 = fmaf(-2.f, acc[nt][1], e1);
                float s10 = fmaf(-2.f, acc[nt][2], e0);
                float s11 = fmaf(-2.f, acc[nt][3], e1);
                if (s00 < s1a) { s2a = s1a; s1a = s00; i1a = n0; } else s2a = fminf(s2a, s00);
                if (s01 < s1a) { s2a = s1a; s1a = s01; i1a = n0 + 1; } else s2a = fminf(s2a, s01);
                if (s10 < s1b) { s2b = s1b; s1b = s10; i1b = n0; } else s2b = fminf(s2b, s10);
                if (s11 < s1b) { s2b = s1b; s1b = s11; i1b = n0 + 1; } else s2b = fminf(s2b, s11);
            }
        }
        __syncthreads();
    }

    // ---- quad reduction of (best, idx, second) ----
    #pragma unroll
    for (int off = 1; off <= 2; off <<= 1) {
        float o1 = __shfl_xor_sync(0xffffffffu, s1a, off);
        int   oi = __shfl_xor_sync(0xffffffffu, i1a, off);
        float o2 = __shfl_xor_sync(0xffffffffu, s2a, off);
        if (o1 < s1a || (o1 == s1a && oi < i1a)) { s2a = fminf(s1a, o2); s1a = o1; i1a = oi; }
        else                                     { s2a = fminf(s2a, o1); }
        o1 = __shfl_xor_sync(0xffffffffu, s1b, off);
        oi = __shfl_xor_sync(0xffffffffu, i1b, off);
        o2 = __shfl_xor_sync(0xffffffffu, s2b, off);
        if (o1 < s1b || (o1 == s1b && oi < i1b)) { s2b = fminf(s1b, o2); s1b = o1; i1b = oi; }
        else                                     { s2b = fminf(s2b, o1); }
    }
    if (tc == 0) {
        s_bidx[warp * 16 + g]     = i1a;  s_gap[warp * 16 + g]     = s2a - s1a;
        s_bidx[warp * 16 + g + 8] = i1b;  s_gap[warp * 16 + g + 8] = s2b - s1b;
    }
    __syncthreads();

    // ---- certification: flag uncertain points for exact fallback ----
    const float emax2 = __int_as_float(g_emax2_bits);
    if (t < MT) {
        float tau = 3.1e-5f * (s_nz2[t] + emax2);
        int b = s_bidx[t];
        if (s_gap[t] <= tau) {
            int slot = atomicAdd(&g_nflag, 1);
            g_flaglist[slot] = pt0 + t;
            s_bidx[t] = -1;
        } else {
            out_idx[pt0 + t] = (float)b;
            atomicAdd(&g_counts[b], 1.f);
        }
    }
    __syncthreads();

    // ---- epilogue for certified points ----
    float lsum = 0.f;
    #pragma unroll
    for (int r = 0; r < 8; r++) {
        int id = t + BLOCK * r;          // 128 pts x 16 float4-units
        int p = id >> 4, q = id & 15;
        int b = s_bidx[p];
        if (b >= 0) {
            int pt = pt0 + p;
            float4 qv = *(const float4*)(emb + (size_t)b * D_DIM + q * 4);
            float4 zv = *(const float4*)(z + (size_t)pt * D_DIM + q * 4);
            *(float4*)(out_zq + (size_t)pt * D_DIM + q * 4) = qv;
            float dx = zv.x - qv.x, dy = zv.y - qv.y;
            float dz2 = zv.z - qv.z, dw = zv.w - qv.w;
            lsum += dx * dx + dy * dy + dz2 * dz2 + dw * dw;
            float* esum = g_embed_sum + (size_t)b * D_DIM + q * 4;
            atomicAdd(esum + 0, zv.x);
            atomicAdd(esum + 1, zv.y);
            atomicAdd(esum + 2, zv.z);
            atomicAdd(esum + 3, zv.w);
        }
    }

    sred[t] = lsum;
    __syncthreads();
    for (int s = BLOCK / 2; s > 0; s >>= 1) {
        if (t < s) sred[t] += sred[t + s];
        __syncthreads();
    }
    if (t == 0) atomicAdd(&g_loss_sum, sred[0]);
}

// -------- fallback: BLOCK-per-point exact fp32 argmin (short critical path) --------
#define FB_BLOCKS 2048
__global__ __launch_bounds__(256) void fallback_kernel(
    const float* __restrict__ z, const float* __restrict__ emb,
    float* __restrict__ out_zq, float* __restrict__ out_idx)
{
    __shared__ float zs[D_DIM];
    __shared__ float wbest[8];
    __shared__ int   wbidx[8];

    const int nflag = g_nflag;
    const int t = threadIdx.x, lane = t & 31, warp = t >> 5;

    for (int i = blockIdx.x; i < nflag; i += FB_BLOCKS) {
        const int pt = g_flaglist[i];
        if (t < 16) ((float4*)zs)[t] = ((const float4*)(z + (size_t)pt * D_DIM))[t];
        __syncthreads();

        float best = FLT_MAX; int bi = 0x7fffffff;
        #pragma unroll
        for (int c = 0; c < 4; c++) {           // thread t owns codes c*256 + t
            int e = c * 256 + t;
            const float4* er = (const float4*)(emb + (size_t)e * D_DIM);
            float a0 = 0.f, a1 = 0.f, a2 = 0.f, a3 = 0.f;
            #pragma unroll
            for (int q = 0; q < 16; q++) {
                float4 ev = er[q];
                a0 = fmaf(ev.x, zs[4 * q + 0], a0);
                a1 = fmaf(ev.y, zs[4 * q + 1], a1);
                a2 = fmaf(ev.z, zs[4 * q + 2], a2);
                a3 = fmaf(ev.w, zs[4 * q + 3], a3);
            }
            float s = g_enorm[e] - 2.f * ((a0 + a1) + (a2 + a3));
            if (s < best || (s == best && e < bi)) { best = s; bi = e; }
        }
        #pragma unroll
        for (int off = 16; off > 0; off >>= 1) {
            float s2 = __shfl_xor_sync(0xffffffffu, best, off);
            int   b2 = __shfl_xor_sync(0xffffffffu, bi, off);
            if (s2 < best || (s2 == best && b2 < bi)) { best = s2; bi = b2; }
        }
        if (lane == 0) { wbest[warp] = best; wbidx[warp] = bi; }
        __syncthreads();
        if (warp == 0) {
            best = (lane < 8) ? wbest[lane] : FLT_MAX;
            bi   = (lane < 8) ? wbidx[lane] : 0x7fffffff;
            #pragma unroll
            for (int off = 4; off > 0; off >>= 1) {
                float s2 = __shfl_xor_sync(0xffffffffu, best, off);
                int   b2 = __shfl_xor_sync(0xffffffffu, bi, off);
                if (s2 < best || (s2 == best && b2 < bi)) { best = s2; bi = b2; }
            }
            if (lane == 0) { wbidx[0] = bi; }
        }
        __syncthreads();
        bi = wbidx[0];

        float lsum = 0.f;
        if (t < 16) {
            float4 qv = *(const float4*)(emb + (size_t)bi * D_DIM + t * 4);
            float4 zv = ((const float4*)zs)[t];
            *(float4*)(out_zq + (size_t)pt * D_DIM + t * 4) = qv;
            float dx = zv.x - qv.x, dy = zv.y - qv.y;
            float dz2 = zv.z - qv.z, dw = zv.w - qv.w;
            lsum = dx * dx + dy * dy + dz2 * dz2 + dw * dw;
            float* esum = g_embed_sum + (size_t)bi * D_DIM + t * 4;
            atomicAdd(esum + 0, zv.x);
            atomicAdd(esum + 1, zv.y);
            atomicAdd(esum + 2, zv.z);
            atomicAdd(esum + 3, zv.w);
        }
        if (warp == 0) {
            #pragma unroll
            for (int off = 16; off > 0; off >>= 1)
                lsum += __shfl_xor_sync(0xffffffffu, lsum, off);
            if (lane == 0) {
                out_idx[pt] = (float)bi;
                atomicAdd(&g_counts[bi], 1.f);
                atomicAdd(&g_loss_sum, lsum);
            }
        }
        __syncthreads();   // zs/wbest reuse next iteration
    }
}

// -------- finalize_cs: cluster-size EMA, n-sum, inv factors, loss (1 CTA) --------
__global__ __launch_bounds__(1024) void finalize_cs(
    const float* __restrict__ cluster_size,
    float* __restrict__ out_loss, float* __restrict__ out_ncs)
{
    __shared__ float sred[1024];
    const int t = threadIdx.x;   // one CTA, 1024 threads (== K)

    float c = cluster_size[t] * DECAY + ONE_MINUS_DECAY * g_counts[t];
    out_ncs[t] = c;
    sred[t] = c;
    __syncthreads();
    for (int s = 512; s > 0; s >>= 1) {
        if (t < s) sred[t] += sred[t + s];
        __syncthreads();
    }
    float n = sred[0];
    float cs = (c + EPSV) / (n + (float)K_EMB * EPSV) * n;
    g_inv[t] = 1.f / cs;
    if (t == 0) out_loss[0] = g_loss_sum / (float)((size_t)N_PTS * D_DIM);
}

// -------- finalize_emb: coalesced scalar EMA + normalize (256 CTAs) --------
// NOTE: out_nemb/out_nema sit at ODD float offsets in d_out (the scalar loss
// shifts everything by 1 float), so vectorized stores are illegal. Scalar
// 4B-per-lane accesses are still fully coalesced (8 sectors/warp).
__global__ __launch_bounds__(256) void finalize_emb(
    const float* __restrict__ ema,
    float* __restrict__ out_nemb, float* __restrict__ out_nema)
{
    int idx = blockIdx.x * 256 + threadIdx.x;        // 65536 elements
    int row = idx >> 6;
    float inv = g_inv[row];
    float o = ema[idx] * DECAY + ONE_MINUS_DECAY * g_embed_sum[idx];
    out_nema[idx] = o;
    out_nemb[idx] = o * inv;
}

// -------- launch --------
extern "C" void kernel_launch(void* const* d_in, const int* in_sizes, int n_in,
                              void* d_out, int out_size) {
    const float* z   = (const float*)d_in[0];
    const float* emb = (const float*)d_in[1];
    const float* cs  = (const float*)d_in[2];
    const float* ema = (const float*)d_in[3];

    float* out      = (float*)d_out;
    float* out_zq   = out;                               // N*D
    float* out_loss = out + (size_t)N_PTS * D_DIM;       // 1
    float* out_idx  = out_loss + 1;                      // N
    float* out_nemb = out_idx + N_PTS;                   // K*D
    float* out_ncs  = out_nemb + (size_t)K_EMB * D_DIM;  // K
    float* out_nema = out_ncs + K_EMB;                   // K*D

    cudaFuncSetAttribute(vq_main, cudaFuncAttributeMaxDynamicSharedMemorySize,
                         SMEM_TOTAL);

    zero_kernel<<<1, 1>>>();                             // launch 0
    prep_kernel<<<256, 256>>>(emb);                      // launch 1
    dummy_kernel<<<1, 1>>>();                            // launch 2 (ncu padding)
    vq_main<<<N_PTS / MT, BLOCK, SMEM_TOTAL>>>(z, emb, out_zq, out_idx);  // launch 3
    fallback_kernel<<<FB_BLOCKS, 256>>>(z, emb, out_zq, out_idx);         // launch 4
    finalize_cs<<<1, 1024>>>(cs, out_loss, out_ncs);                      // launch 5
    finalize_emb<<<256, 256>>>(ema, out_nemb, out_nema);                  // launch 6
}